// round 8
// baseline (speedup 1.0000x reference)
#include <cuda_runtime.h>
#include <cuda_bf16.h>
#include <math.h>
#include <stdint.h>

// ---------------------------------------------------------------------------
// Problem dims (fixed): a=b=8192, e1=e2=c=m=1024
constexpr int KDIM = 1024;
constexpr int A_MAX = 8192;

constexpr int BM = 256;                 // CTA M tile
constexpr int BN = 128;                 // CTA N tile
constexpr int KC = 64;                  // K chunk (bf16): 128 B per row
constexpr int NCHUNK = KDIM / KC;       // 16
constexpr int TILEA_B = BM * 128;       // 32768 B (A tile per stage)
constexpr int TILEB_B = BN * 128;       // 16384 B (B tile per stage)
constexpr int STAGE_B = TILEA_B + TILEB_B;  // 49152
constexpr int NSTAGE = 3;
constexpr int SMEM_DYN = NSTAGE * STAGE_B;  // 147456 B

// ---------------------------------------------------------------------------
// Device-global scratch
static __device__ __nv_bfloat16 g_x1[(size_t)A_MAX * KDIM];   // seq1 bf16
static __device__ __nv_bfloat16 g_x2[(size_t)A_MAX * KDIM];   // seq2 bf16
static __device__ __nv_bfloat16 g_wt1[(size_t)KDIM * KDIM];   // W1 bf16
static __device__ __nv_bfloat16 g_wt2[(size_t)KDIM * KDIM];   // W2 bf16
static __device__ __nv_bfloat16 g_p1[(size_t)A_MAX * KDIM];
static __device__ __nv_bfloat16 g_p2[(size_t)A_MAX * KDIM];
static __device__ float g_cvec[2 * KDIM];
static __device__ float g_s[2 * KDIM];
static __device__ float g_logits[2 * A_MAX];
static __device__ float g_w[2 * A_MAX];

// ---------------------------------------------------------------------------
__device__ __forceinline__ uint32_t smem_u32(const void* p) {
    uint32_t a;
    asm("{ .reg .u64 t; cvta.to.shared.u64 t, %1; cvt.u32.u64 %0, t; }" : "=r"(a) : "l"(p));
    return a;
}
__device__ __forceinline__ void cp16(uint32_t smem, const void* g) {
    asm volatile("cp.async.cg.shared.global [%0], [%1], 16;" :: "r"(smem), "l"(g) : "memory");
}
__device__ __forceinline__ void cp_commit() {
    asm volatile("cp.async.commit_group;" ::: "memory");
}
template <int N>
__device__ __forceinline__ void cp_wait() {
    asm volatile("cp.async.wait_group %0;" :: "n"(N) : "memory");
}
__device__ __forceinline__ void ldsm_x4(uint32_t addr, uint32_t* r) {
    asm volatile("ldmatrix.sync.aligned.m8n8.x4.shared.b16 {%0,%1,%2,%3}, [%4];"
                 : "=r"(r[0]), "=r"(r[1]), "=r"(r[2]), "=r"(r[3]) : "r"(addr));
}
__device__ __forceinline__ void mma16816(float* d, const uint32_t* a, const uint32_t* b) {
    asm volatile(
        "mma.sync.aligned.m16n8k16.row.col.f32.bf16.bf16.f32 "
        "{%0,%1,%2,%3}, {%4,%5,%6,%7}, {%8,%9}, {%0,%1,%2,%3};\n"
        : "+f"(d[0]), "+f"(d[1]), "+f"(d[2]), "+f"(d[3])
        : "r"(a[0]), "r"(a[1]), "r"(a[2]), "r"(a[3]), "r"(b[0]), "r"(b[1]));
}

// ---------------------------------------------------------------------------
__global__ void k_init(float* out, int out_n) {
    int i = blockIdx.x * blockDim.x + threadIdx.x;
    if (i < 2 * KDIM) g_s[i] = 0.f;
    if (i < out_n)    out[i] = 0.f;
}

// All four fp32->bf16 conversions in one launch. Segments (in 8-elem units):
// [0, NSEQ8) seq1->g_x1, [NSEQ8, 2*NSEQ8) seq2->g_x2,
// [2*NSEQ8, +NW8) W1->g_wt1, [.., +NW8) W2->g_wt2.
constexpr int NSEQ8 = A_MAX * KDIM / 8;     // 1048576
constexpr int NW8   = KDIM * KDIM / 8;      // 131072
constexpr int NCONV = 2 * NSEQ8 + 2 * NW8;  // 2359296

__global__ void k_tobf16_all(const float4* __restrict__ s1, const float4* __restrict__ s2,
                             const float4* __restrict__ w1, const float4* __restrict__ w2) {
    int i = blockIdx.x * blockDim.x + threadIdx.x;
    if (i >= NCONV) return;
    const float4* src;
    uint4* dst;
    int off;
    if (i < NSEQ8)            { src = s1; dst = (uint4*)g_x1;  off = i; }
    else if (i < 2 * NSEQ8)   { src = s2; dst = (uint4*)g_x2;  off = i - NSEQ8; }
    else if (i < 2 * NSEQ8 + NW8) { src = w1; dst = (uint4*)g_wt1; off = i - 2 * NSEQ8; }
    else                      { src = w2; dst = (uint4*)g_wt2; off = i - 2 * NSEQ8 - NW8; }
    float4 v0 = src[2 * off], v1 = src[2 * off + 1];
    uint4 o;
    __nv_bfloat162 t;
    t = __floats2bfloat162_rn(v0.x, v0.y); o.x = *(uint32_t*)&t;
    t = __floats2bfloat162_rn(v0.z, v0.w); o.y = *(uint32_t*)&t;
    t = __floats2bfloat162_rn(v1.x, v1.y); o.z = *(uint32_t*)&t;
    t = __floats2bfloat162_rn(v1.z, v1.w); o.w = *(uint32_t*)&t;
    dst[off] = o;
}

// cvec for both branches in one launch: blockIdx.y = which
__global__ void k_cvec(const float* __restrict__ Wc1x, const float* __restrict__ Wc2x,
                       const float* __restrict__ b1x, const float* __restrict__ b2x,
                       const float* __restrict__ ctx) {
    const int which = blockIdx.y;
    const float* Wc = which ? Wc2x : Wc1x;
    const float* bias = which ? b2x : b1x;
    int warp = (blockIdx.x * blockDim.x + threadIdx.x) >> 5;
    int lane = threadIdx.x & 31;
    if (warp >= KDIM) return;
    const float4* wrow = (const float4*)(Wc + (size_t)warp * KDIM);
    const float4* c4   = (const float4*)ctx;
    float sum = 0.f;
#pragma unroll
    for (int it = 0; it < KDIM / 128; ++it) {
        float4 wv = wrow[lane + it * 32];
        float4 cv = c4[lane + it * 32];
        sum += wv.x * cv.x + wv.y * cv.y + wv.z * cv.z + wv.w * cv.w;
    }
#pragma unroll
    for (int o = 16; o; o >>= 1) sum += __shfl_xor_sync(0xffffffffu, sum, o);
    if (lane == 0) g_cvec[which * KDIM + warp] = sum + bias[warp];
}

// ---------------------------------------------------------------------------
// P = elu(X @ Wt.T + cvec). 256x128 tile, 512 threads = 16 warps (4x4 grid,
// 64x32 per warp), 3-stage cp.async, ldmatrix + mma.sync. blockIdx.z = branch.
__global__ __launch_bounds__(512, 1)
void k_proj_mma() {
    extern __shared__ char dynsm[];
    const uint32_t sb = smem_u32(dynsm);

    const int which = blockIdx.z;
    const __nv_bfloat16* __restrict__ X  = which ? g_x2  : g_x1;
    const __nv_bfloat16* __restrict__ Wt = which ? g_wt2 : g_wt1;
    __nv_bfloat16* __restrict__ P = which ? g_p2 : g_p1;
    const float* __restrict__ cvec = g_cvec + which * KDIM;
    float* __restrict__ scol = g_s + which * KDIM;

    const int tid  = threadIdx.x;
    const int wid  = tid >> 5;
    const int lane = tid & 31;
    const int warpRow = wid & 3;        // 0..3 -> rows 64*warpRow
    const int warpCol = wid >> 2;       // 0..3 -> cols 32*warpCol
    const int rowBase = blockIdx.y * BM;
    const int colBase = blockIdx.x * BN;

    // cp.async mapping: row = tid>>3 (0..63), kcol = tid&7 (16B units)
    const int cprow = tid >> 3;
    const int cpcol = tid & 7;
    const uint32_t cpswz = (uint32_t)((cpcol ^ (cprow & 7)) << 4);
    const __nv_bfloat16* gA = X  + (size_t)(rowBase + cprow) * KDIM + cpcol * 8;
    const __nv_bfloat16* gB = Wt + (size_t)(colBase + cprow) * KDIM + cpcol * 8;

    // ldmatrix addressing (row&7 == laneQ for all frag rows)
    const int laneQ = lane & 7;
    const int blkId = lane >> 3;
    const uint32_t aKc0 = (uint32_t)(blkId >> 1);
    const uint32_t bKc0 = (uint32_t)(blkId & 1);
    uint32_t aRowOff[4], bRowOff[2];
#pragma unroll
    for (int rb = 0; rb < 4; ++rb)
        aRowOff[rb] = (uint32_t)(warpRow * 64 + rb * 16 + (blkId & 1) * 8 + laneQ) * 128u;
#pragma unroll
    for (int pr = 0; pr < 2; ++pr)
        bRowOff[pr] = (uint32_t)(warpCol * 32 + pr * 16 + (blkId >> 1) * 8 + laneQ) * 128u;

    float acc[4][4][4] = {};

    // issue copy of chunk c into stage s: A = 4 cp16/thread, B = 2 cp16/thread
    auto issue = [&](int s, int c) {
        const uint32_t stg = sb + (uint32_t)s * STAGE_B;
        const int ko = c * KC;
#pragma unroll
        for (int it = 0; it < 4; ++it) {
            uint32_t soff = (uint32_t)(cprow + 64 * it) * 128u + cpswz;
            cp16(stg + soff, gA + (size_t)(64 * it) * KDIM + ko);
        }
#pragma unroll
        for (int it = 0; it < 2; ++it) {
            uint32_t soff = (uint32_t)(cprow + 64 * it) * 128u + cpswz;
            cp16(stg + TILEA_B + soff, gB + (size_t)(64 * it) * KDIM + ko);
        }
        cp_commit();
    };

    issue(0, 0);
    issue(1, 1);

    int stage = 0;
    for (int c = 0; c < NCHUNK; ++c) {
        if (c == NCHUNK - 1) cp_wait<0>(); else cp_wait<1>();
        __syncthreads();

        const uint32_t smA = sb + (uint32_t)stage * STAGE_B;
        const uint32_t smB = smA + TILEA_B;
#pragma unroll
        for (int ks = 0; ks < 4; ++ks) {
            uint32_t af[4][4], bf[2][4];
            const uint32_t aSw = (uint32_t)(((ks * 2 + aKc0) ^ laneQ) << 4);
            const uint32_t bSw = (uint32_t)(((ks * 2 + bKc0) ^ laneQ) << 4);
#pragma unroll
            for (int rb = 0; rb < 4; ++rb)
                ldsm_x4(smA + aRowOff[rb] + aSw, af[rb]);
#pragma unroll
            for (int pr = 0; pr < 2; ++pr)
                ldsm_x4(smB + bRowOff[pr] + bSw, bf[pr]);
#pragma unroll
            for (int cf = 0; cf < 4; ++cf) {
                const uint32_t* bp = &bf[cf >> 1][(cf & 1) * 2];
#pragma unroll
                for (int rb = 0; rb < 4; ++rb)
                    mma16816(acc[rb][cf], af[rb], bp);
            }
        }

        if (c + 2 < NCHUNK) issue((stage + 2) % NSTAGE, c + 2);
        stage = (stage + 1) % NSTAGE;
    }

    // ---- epilogue: +cvec, ELU, bf16 store, column sums ----
    const int gq  = lane >> 2;
    const int tig = lane & 3;
    float csum[8];
#pragma unroll
    for (int j = 0; j < 8; ++j) csum[j] = 0.f;

#pragma unroll
    for (int rb = 0; rb < 4; ++rb) {
#pragma unroll
        for (int cf = 0; cf < 4; ++cf) {
            const int col = colBase + warpCol * 32 + cf * 8 + tig * 2;
            const float cv0 = cvec[col], cv1 = cvec[col + 1];
#pragma unroll
            for (int half = 0; half < 2; ++half) {
                const int row = rowBase + warpRow * 64 + rb * 16 + gq + half * 8;
                float v0 = acc[rb][cf][half * 2 + 0] + cv0;
                float v1 = acc[rb][cf][half * 2 + 1] + cv1;
                v0 = (v0 > 0.f) ? v0 : expm1f(v0);
                v1 = (v1 > 0.f) ? v1 : expm1f(v1);
                __nv_bfloat162 pk = __floats2bfloat162_rn(v0, v1);
                *(__nv_bfloat162*)(P + (size_t)row * KDIM + col) = pk;
                csum[cf * 2 + 0] += v0;
                csum[cf * 2 + 1] += v1;
            }
        }
    }
#pragma unroll
    for (int j = 0; j < 8; ++j) {
        float v = csum[j];
        v += __shfl_xor_sync(0xffffffffu, v, 4);
        v += __shfl_xor_sync(0xffffffffu, v, 8);
        v += __shfl_xor_sync(0xffffffffu, v, 16);
        if (gq == 0) {
            int col = colBase + warpCol * 32 + (j >> 1) * 8 + tig * 2 + (j & 1);
            atomicAdd(&scol[col], v);
        }
    }
}

// ---------------------------------------------------------------------------
// logits[z][i] = dot(P[z][i,:], g_s[1-z])  (one warp per row; blockIdx.y = z)
__global__ void k_matvec(int M) {
    int warp = (blockIdx.x * blockDim.x + threadIdx.x) >> 5;
    int lane = threadIdx.x & 31;
    if (warp >= M) return;
    const int z = blockIdx.y;
    const __nv_bfloat16* P = z ? g_p2 : g_p1;
    const uint4* pr = (const uint4*)(P + (size_t)warp * KDIM);
    const float4* s4 = (const float4*)(g_s + (1 - z) * KDIM);
    float sum = 0.f;
#pragma unroll
    for (int it = 0; it < KDIM / 256; ++it) {
        uint4 pk = pr[lane + it * 32];
        float4 sa = s4[(lane + it * 32) * 2 + 0];
        float4 sbv = s4[(lane + it * 32) * 2 + 1];
        float2 p0 = __bfloat1622float2(*(const __nv_bfloat162*)&pk.x);
        float2 p1 = __bfloat1622float2(*(const __nv_bfloat162*)&pk.y);
        float2 p2 = __bfloat1622float2(*(const __nv_bfloat162*)&pk.z);
        float2 p3 = __bfloat1622float2(*(const __nv_bfloat162*)&pk.w);
        sum += p0.x * sa.x + p0.y * sa.y + p1.x * sa.z + p1.y * sa.w;
        sum += p2.x * sbv.x + p2.y * sbv.y + p3.x * sbv.z + p3.y * sbv.w;
    }
#pragma unroll
    for (int o = 16; o; o >>= 1) sum += __shfl_xor_sync(0xffffffffu, sum, o);
    if (lane == 0) g_logits[z * A_MAX + warp] = sum;
}

// softmax over n logits; blockIdx.x = which
__global__ void k_softmax(int n) {
    __shared__ float sbuf[1024];
    const int which = blockIdx.x;
    const float* logits = g_logits + which * A_MAX;
    float* w = g_w + which * A_MAX;
    int tid = threadIdx.x;

    float mx = -3.4e38f;
    for (int i = tid; i < n; i += 1024) mx = fmaxf(mx, logits[i]);
    sbuf[tid] = mx; __syncthreads();
    for (int o = 512; o; o >>= 1) {
        if (tid < o) sbuf[tid] = fmaxf(sbuf[tid], sbuf[tid + o]);
        __syncthreads();
    }
    mx = sbuf[0]; __syncthreads();

    float se = 0.f;
    for (int i = tid; i < n; i += 1024) se += expf(logits[i] - mx);
    sbuf[tid] = se; __syncthreads();
    for (int o = 512; o; o >>= 1) {
        if (tid < o) sbuf[tid] += sbuf[tid + o];
        __syncthreads();
    }
    float inv = 1.f / sbuf[0];

    for (int i = tid; i < n; i += 1024) w[i] = expf(logits[i] - mx) * inv;
}

// out[z*KDIM + col4] += sum_r w[z][r] * seq_z[r, col4]; float4 per thread
__global__ void k_pool(const float* __restrict__ seq1, const float* __restrict__ seq2,
                       float* __restrict__ out, int rowsPerBlock) {
    const int z = blockIdx.z;
    const float* seq = z ? seq2 : seq1;
    const float* w = g_w + z * A_MAX;
    const int c4 = threadIdx.x;           // 0..255 -> cols c4*4
    const int r0 = blockIdx.y * rowsPerBlock;
    float4 acc = {0.f, 0.f, 0.f, 0.f};
    for (int r = r0; r < r0 + rowsPerBlock; ++r) {
        float wr = w[r];
        float4 v = *(const float4*)(seq + (size_t)r * KDIM + c4 * 4);
        acc.x += wr * v.x; acc.y += wr * v.y; acc.z += wr * v.z; acc.w += wr * v.w;
    }
    float* o = out + z * KDIM + c4 * 4;
    atomicAdd(o + 0, acc.x);
    atomicAdd(o + 1, acc.y);
    atomicAdd(o + 2, acc.z);
    atomicAdd(o + 3, acc.w);
}

// ---------------------------------------------------------------------------
extern "C" void kernel_launch(void* const* d_in, const int* in_sizes, int n_in,
                              void* d_out, int out_size) {
    const float* seq1 = (const float*)d_in[0];
    const float* seq2 = (const float*)d_in[1];
    const float* ctx  = (const float*)d_in[2];
    const float* Wc1  = (const float*)d_in[3];
    const float* W1   = (const float*)d_in[4];
    const float* b1   = (const float*)d_in[5];
    const float* Wc2  = (const float*)d_in[6];
    const float* W2   = (const float*)d_in[7];
    const float* b2   = (const float*)d_in[8];
    float* out = (float*)d_out;

    const int a = in_sizes[0] / KDIM;   // 8192
    const int b = in_sizes[1] / KDIM;   // 8192

    cudaFuncSetAttribute(k_proj_mma, cudaFuncAttributeMaxDynamicSharedMemorySize, SMEM_DYN);

    k_init<<<(2 * KDIM + 255) / 256, 256>>>(out, out_size);

    {
        dim3 gc(KDIM / 8, 2);
        k_cvec<<<gc, 256>>>(Wc1, Wc2, b1, b2, ctx);
    }

    k_tobf16_all<<<(NCONV + 255) / 256, 256>>>((const float4*)seq1, (const float4*)seq2,
                                               (const float4*)W1, (const float4*)W2);

    {
        dim3 g(KDIM / BN, a / BM, 2);
        k_proj_mma<<<g, 512, SMEM_DYN>>>();
    }

    {
        dim3 gm((a + 7) / 8, 2);
        k_matvec<<<gm, 256>>>(a);
    }

    k_softmax<<<2, 1024>>>(a);

    {
        const int RPB = 32;
        dim3 gp(1, a / RPB, 2);
        k_pool<<<gp, 256>>>(seq1, seq2, out, RPB);
    }
}

// round 9
// speedup vs baseline: 1.1074x; 1.1074x over previous
#include <cuda_runtime.h>
#include <cuda_bf16.h>
#include <math.h>
#include <stdint.h>

// ---------------------------------------------------------------------------
// Problem dims (fixed): a=b=8192, e1=e2=c=m=1024
constexpr int KDIM = 1024;
constexpr int A_MAX = 8192;

constexpr int BM = 128;
constexpr int BN = 128;
constexpr int KC = 64;                  // K chunk (bf16): 128 B per row
constexpr int NCHUNK = KDIM / KC;       // 16
constexpr int TILE_B = BM * 128;        // 16384 B per tile (128B rows)
constexpr int STAGE_B = 2 * TILE_B;     // A + B per stage = 32768
constexpr int NSTAGE = 3;
constexpr int SMEM_DYN = NSTAGE * STAGE_B;  // 98304 B per CTA (2 CTAs = 192KB)

// ---------------------------------------------------------------------------
// Device-global scratch
static __device__ __nv_bfloat16 g_x1[(size_t)A_MAX * KDIM];   // seq1 bf16
static __device__ __nv_bfloat16 g_x2[(size_t)A_MAX * KDIM];   // seq2 bf16
static __device__ __nv_bfloat16 g_wt1[(size_t)KDIM * KDIM];   // W1 bf16
static __device__ __nv_bfloat16 g_wt2[(size_t)KDIM * KDIM];   // W2 bf16
static __device__ __nv_bfloat16 g_p1[(size_t)A_MAX * KDIM];
static __device__ __nv_bfloat16 g_p2[(size_t)A_MAX * KDIM];
static __device__ float g_cvec[2 * KDIM];
static __device__ float g_s[2 * KDIM];
static __device__ float g_logits[2 * A_MAX];
static __device__ float g_w[2 * A_MAX];

// ---------------------------------------------------------------------------
__device__ __forceinline__ uint32_t smem_u32(const void* p) {
    uint32_t a;
    asm("{ .reg .u64 t; cvta.to.shared.u64 t, %1; cvt.u32.u64 %0, t; }" : "=r"(a) : "l"(p));
    return a;
}
__device__ __forceinline__ void cp16(uint32_t smem, const void* g) {
    asm volatile("cp.async.cg.shared.global [%0], [%1], 16;" :: "r"(smem), "l"(g) : "memory");
}
__device__ __forceinline__ void cp_commit() {
    asm volatile("cp.async.commit_group;" ::: "memory");
}
template <int N>
__device__ __forceinline__ void cp_wait() {
    asm volatile("cp.async.wait_group %0;" :: "n"(N) : "memory");
}
__device__ __forceinline__ void ldsm_x4(uint32_t addr, uint32_t* r) {
    asm volatile("ldmatrix.sync.aligned.m8n8.x4.shared.b16 {%0,%1,%2,%3}, [%4];"
                 : "=r"(r[0]), "=r"(r[1]), "=r"(r[2]), "=r"(r[3]) : "r"(addr));
}
__device__ __forceinline__ void mma16816(float* d, const uint32_t* a, const uint32_t* b) {
    asm volatile(
        "mma.sync.aligned.m16n8k16.row.col.f32.bf16.bf16.f32 "
        "{%0,%1,%2,%3}, {%4,%5,%6,%7}, {%8,%9}, {%0,%1,%2,%3};\n"
        : "+f"(d[0]), "+f"(d[1]), "+f"(d[2]), "+f"(d[3])
        : "r"(a[0]), "r"(a[1]), "r"(a[2]), "r"(a[3]), "r"(b[0]), "r"(b[1]));
}

// ---------------------------------------------------------------------------
__global__ void k_init(float* out, int out_n) {
    int i = blockIdx.x * blockDim.x + threadIdx.x;
    if (i < 2 * KDIM) g_s[i] = 0.f;
    if (i < out_n)    out[i] = 0.f;
}

// All four fp32->bf16 conversions, one launch, grid-stride, 16 elems/thread.
constexpr int NSEQ8 = A_MAX * KDIM / 8;     // 1048576 (8-elem units)
constexpr int NW8   = KDIM * KDIM / 8;      // 131072
constexpr int NCONV = 2 * NSEQ8 + 2 * NW8;  // 2359296 8-elem units

__global__ void k_tobf16_all(const float4* __restrict__ s1, const float4* __restrict__ s2,
                             const float4* __restrict__ w1, const float4* __restrict__ w2) {
    const int stride = gridDim.x * blockDim.x;
    for (int u = blockIdx.x * blockDim.x + threadIdx.x; u < NCONV / 2; u += stride) {
        // each u handles two consecutive 8-elem units (16 elems)
        int i = 2 * u;
        const float4* src;
        uint4* dst;
        int off;
        if (i < NSEQ8)                 { src = s1; dst = (uint4*)g_x1;  off = i; }
        else if (i < 2 * NSEQ8)        { src = s2; dst = (uint4*)g_x2;  off = i - NSEQ8; }
        else if (i < 2 * NSEQ8 + NW8)  { src = w1; dst = (uint4*)g_wt1; off = i - 2 * NSEQ8; }
        else                           { src = w2; dst = (uint4*)g_wt2; off = i - 2 * NSEQ8 - NW8; }
        float4 v0 = src[2 * off + 0], v1 = src[2 * off + 1];
        float4 v2 = src[2 * off + 2], v3 = src[2 * off + 3];
        uint4 o0, o1;
        __nv_bfloat162 t;
        t = __floats2bfloat162_rn(v0.x, v0.y); o0.x = *(uint32_t*)&t;
        t = __floats2bfloat162_rn(v0.z, v0.w); o0.y = *(uint32_t*)&t;
        t = __floats2bfloat162_rn(v1.x, v1.y); o0.z = *(uint32_t*)&t;
        t = __floats2bfloat162_rn(v1.z, v1.w); o0.w = *(uint32_t*)&t;
        t = __floats2bfloat162_rn(v2.x, v2.y); o1.x = *(uint32_t*)&t;
        t = __floats2bfloat162_rn(v2.z, v2.w); o1.y = *(uint32_t*)&t;
        t = __floats2bfloat162_rn(v3.x, v3.y); o1.z = *(uint32_t*)&t;
        t = __floats2bfloat162_rn(v3.z, v3.w); o1.w = *(uint32_t*)&t;
        dst[off + 0] = o0;
        dst[off + 1] = o1;
    }
}

// cvec for both branches in one launch: blockIdx.y = which
__global__ void k_cvec(const float* __restrict__ Wc1x, const float* __restrict__ Wc2x,
                       const float* __restrict__ b1x, const float* __restrict__ b2x,
                       const float* __restrict__ ctx) {
    const int which = blockIdx.y;
    const float* Wc = which ? Wc2x : Wc1x;
    const float* bias = which ? b2x : b1x;
    int warp = (blockIdx.x * blockDim.x + threadIdx.x) >> 5;
    int lane = threadIdx.x & 31;
    if (warp >= KDIM) return;
    const float4* wrow = (const float4*)(Wc + (size_t)warp * KDIM);
    const float4* c4   = (const float4*)ctx;
    float sum = 0.f;
#pragma unroll
    for (int it = 0; it < KDIM / 128; ++it) {
        float4 wv = wrow[lane + it * 32];
        float4 cv = c4[lane + it * 32];
        sum += wv.x * cv.x + wv.y * cv.y + wv.z * cv.z + wv.w * cv.w;
    }
#pragma unroll
    for (int o = 16; o; o >>= 1) sum += __shfl_xor_sync(0xffffffffu, sum, o);
    if (lane == 0) g_cvec[which * KDIM + warp] = sum + bias[warp];
}

// ---------------------------------------------------------------------------
// P = elu(X @ Wt.T + cvec). bf16 inputs, cp.async 3-stage pipeline,
// ldmatrix + mma.sync. 256 threads = 8 warps (2x4 grid, 64x32 per warp),
// 2 CTAs/SM. blockIdx.z = branch. (R7-passing configuration.)
__global__ __launch_bounds__(256, 2)
void k_proj_mma() {
    extern __shared__ char dynsm[];
    const uint32_t sb = smem_u32(dynsm);

    const int which = blockIdx.z;
    const __nv_bfloat16* __restrict__ X  = which ? g_x2  : g_x1;
    const __nv_bfloat16* __restrict__ Wt = which ? g_wt2 : g_wt1;
    __nv_bfloat16* __restrict__ P = which ? g_p2 : g_p1;
    const float* __restrict__ cvec = g_cvec + which * KDIM;
    float* __restrict__ scol = g_s + which * KDIM;

    const int tid  = threadIdx.x;
    const int wid  = tid >> 5;
    const int lane = tid & 31;
    const int warpRow = wid & 1;        // 0..1 -> rows 64*warpRow
    const int warpCol = wid >> 1;       // 0..3 -> cols 32*warpCol
    const int rowBase = blockIdx.y * BM;
    const int colBase = blockIdx.x * BN;

    // cp.async mapping: idx = tid + it*256; row = idx>>3, kcol = idx&7 (16B units)
    const int cprow = tid >> 3;         // 0..31, advances by 32 per it
    const int cpcol = tid & 7;
    const uint32_t cpswz = (uint32_t)((cpcol ^ (cprow & 7)) << 4);
    const __nv_bfloat16* gA = X  + (size_t)(rowBase + cprow) * KDIM + cpcol * 8;
    const __nv_bfloat16* gB = Wt + (size_t)(colBase + cprow) * KDIM + cpcol * 8;

    // ldmatrix addressing (row&7 == laneQ for all frag rows)
    const int laneQ = lane & 7;
    const int blkId = lane >> 3;
    const uint32_t aKc0 = (uint32_t)(blkId >> 1);    // A kcol low bit
    const uint32_t bKc0 = (uint32_t)(blkId & 1);     // B kcol low bit
    uint32_t aRowOff[4], bRowOff[2];
#pragma unroll
    for (int rb = 0; rb < 4; ++rb)
        aRowOff[rb] = (uint32_t)(warpRow * 64 + rb * 16 + (blkId & 1) * 8 + laneQ) * 128u;
#pragma unroll
    for (int pr = 0; pr < 2; ++pr)
        bRowOff[pr] = (uint32_t)(warpCol * 32 + pr * 16 + (blkId >> 1) * 8 + laneQ) * 128u;

    float acc[4][4][4] = {};

    // issue copy of chunk c into stage s
    auto issue = [&](int s, int c) {
        const uint32_t stg = sb + (uint32_t)s * STAGE_B;
        const int ko = c * KC;
#pragma unroll
        for (int it = 0; it < 4; ++it) {
            uint32_t soff = (uint32_t)(cprow + 32 * it) * 128u + cpswz;
            cp16(stg + soff,          gA + (size_t)(32 * it) * KDIM + ko);
            cp16(stg + TILE_B + soff, gB + (size_t)(32 * it) * KDIM + ko);
        }
        cp_commit();
    };

    issue(0, 0);
    issue(1, 1);

    int stage = 0;
    for (int c = 0; c < NCHUNK; ++c) {
        if (c == NCHUNK - 1) cp_wait<0>(); else cp_wait<1>();
        __syncthreads();

        const uint32_t smA = sb + (uint32_t)stage * STAGE_B;
        const uint32_t smB = smA + TILE_B;
#pragma unroll
        for (int ks = 0; ks < 4; ++ks) {
            uint32_t af[4][4], bf[2][4];
            const uint32_t aSw = (uint32_t)(((ks * 2 + aKc0) ^ laneQ) << 4);
            const uint32_t bSw = (uint32_t)(((ks * 2 + bKc0) ^ laneQ) << 4);
#pragma unroll
            for (int rb = 0; rb < 4; ++rb)
                ldsm_x4(smA + aRowOff[rb] + aSw, af[rb]);
#pragma unroll
            for (int pr = 0; pr < 2; ++pr)
                ldsm_x4(smB + bRowOff[pr] + bSw, bf[pr]);
#pragma unroll
            for (int cf = 0; cf < 4; ++cf) {
                const uint32_t* bp = &bf[cf >> 1][(cf & 1) * 2];
#pragma unroll
                for (int rb = 0; rb < 4; ++rb)
                    mma16816(acc[rb][cf], af[rb], bp);
            }
        }

        if (c + 2 < NCHUNK) issue((stage + 2) % NSTAGE, c + 2);
        stage = (stage + 1) % NSTAGE;
    }

    // ---- epilogue: +cvec, ELU, bf16 store, column sums ----
    const int gq  = lane >> 2;
    const int tig = lane & 3;
    float csum[8];
#pragma unroll
    for (int j = 0; j < 8; ++j) csum[j] = 0.f;

#pragma unroll
    for (int rb = 0; rb < 4; ++rb) {
#pragma unroll
        for (int cf = 0; cf < 4; ++cf) {
            const int col = colBase + warpCol * 32 + cf * 8 + tig * 2;
            const float cv0 = cvec[col], cv1 = cvec[col + 1];
#pragma unroll
            for (int half = 0; half < 2; ++half) {
                const int row = rowBase + warpRow * 64 + rb * 16 + gq + half * 8;
                float v0 = acc[rb][cf][half * 2 + 0] + cv0;
                float v1 = acc[rb][cf][half * 2 + 1] + cv1;
                v0 = (v0 > 0.f) ? v0 : expm1f(v0);
                v1 = (v1 > 0.f) ? v1 : expm1f(v1);
                __nv_bfloat162 pk = __floats2bfloat162_rn(v0, v1);
                *(__nv_bfloat162*)(P + (size_t)row * KDIM + col) = pk;
                csum[cf * 2 + 0] += v0;
                csum[cf * 2 + 1] += v1;
            }
        }
    }
#pragma unroll
    for (int j = 0; j < 8; ++j) {
        float v = csum[j];
        v += __shfl_xor_sync(0xffffffffu, v, 4);
        v += __shfl_xor_sync(0xffffffffu, v, 8);
        v += __shfl_xor_sync(0xffffffffu, v, 16);
        if (gq == 0) {
            int col = colBase + warpCol * 32 + (j >> 1) * 8 + tig * 2 + (j & 1);
            atomicAdd(&scol[col], v);
        }
    }
}

// ---------------------------------------------------------------------------
// logits[z][i] = dot(P[z][i,:], g_s[1-z])  (one warp per row; blockIdx.y = z)
__global__ void k_matvec(int M) {
    int warp = (blockIdx.x * blockDim.x + threadIdx.x) >> 5;
    int lane = threadIdx.x & 31;
    if (warp >= M) return;
    const int z = blockIdx.y;
    const __nv_bfloat16* P = z ? g_p2 : g_p1;
    const uint4* pr = (const uint4*)(P + (size_t)warp * KDIM);
    const float4* s4 = (const float4*)(g_s + (1 - z) * KDIM);
    float sum = 0.f;
#pragma unroll
    for (int it = 0; it < KDIM / 256; ++it) {
        uint4 pk = pr[lane + it * 32];
        float4 sa = s4[(lane + it * 32) * 2 + 0];
        float4 sbv = s4[(lane + it * 32) * 2 + 1];
        float2 p0 = __bfloat1622float2(*(const __nv_bfloat162*)&pk.x);
        float2 p1 = __bfloat1622float2(*(const __nv_bfloat162*)&pk.y);
        float2 p2 = __bfloat1622float2(*(const __nv_bfloat162*)&pk.z);
        float2 p3 = __bfloat1622float2(*(const __nv_bfloat162*)&pk.w);
        sum += p0.x * sa.x + p0.y * sa.y + p1.x * sa.z + p1.y * sa.w;
        sum += p2.x * sbv.x + p2.y * sbv.y + p3.x * sbv.z + p3.y * sbv.w;
    }
#pragma unroll
    for (int o = 16; o; o >>= 1) sum += __shfl_xor_sync(0xffffffffu, sum, o);
    if (lane == 0) g_logits[z * A_MAX + warp] = sum;
}

// softmax over n logits; blockIdx.x = which
__global__ void k_softmax(int n) {
    __shared__ float sbuf[1024];
    const int which = blockIdx.x;
    const float* logits = g_logits + which * A_MAX;
    float* w = g_w + which * A_MAX;
    int tid = threadIdx.x;

    float mx = -3.4e38f;
    for (int i = tid; i < n; i += 1024) mx = fmaxf(mx, logits[i]);
    sbuf[tid] = mx; __syncthreads();
    for (int o = 512; o; o >>= 1) {
        if (tid < o) sbuf[tid] = fmaxf(sbuf[tid], sbuf[tid + o]);
        __syncthreads();
    }
    mx = sbuf[0]; __syncthreads();

    float se = 0.f;
    for (int i = tid; i < n; i += 1024) se += expf(logits[i] - mx);
    sbuf[tid] = se; __syncthreads();
    for (int o = 512; o; o >>= 1) {
        if (tid < o) sbuf[tid] += sbuf[tid + o];
        __syncthreads();
    }
    float inv = 1.f / sbuf[0];

    for (int i = tid; i < n; i += 1024) w[i] = expf(logits[i] - mx) * inv;
}

// out[z*KDIM + col4] += sum_r w[z][r] * seq_z[r, col4]; float4 per thread
__global__ void k_pool(const float* __restrict__ seq1, const float* __restrict__ seq2,
                       float* __restrict__ out, int rowsPerBlock) {
    const int z = blockIdx.z;
    const float* seq = z ? seq2 : seq1;
    const float* w = g_w + z * A_MAX;
    const int c4 = threadIdx.x;           // 0..255 -> cols c4*4
    const int r0 = blockIdx.y * rowsPerBlock;
    float4 acc = {0.f, 0.f, 0.f, 0.f};
    for (int r = r0; r < r0 + rowsPerBlock; ++r) {
        float wr = w[r];
        float4 v = *(const float4*)(seq + (size_t)r * KDIM + c4 * 4);
        acc.x += wr * v.x; acc.y += wr * v.y; acc.z += wr * v.z; acc.w += wr * v.w;
    }
    float* o = out + z * KDIM + c4 * 4;
    atomicAdd(o + 0, acc.x);
    atomicAdd(o + 1, acc.y);
    atomicAdd(o + 2, acc.z);
    atomicAdd(o + 3, acc.w);
}

// ---------------------------------------------------------------------------
extern "C" void kernel_launch(void* const* d_in, const int* in_sizes, int n_in,
                              void* d_out, int out_size) {
    const float* seq1 = (const float*)d_in[0];
    const float* seq2 = (const float*)d_in[1];
    const float* ctx  = (const float*)d_in[2];
    const float* Wc1  = (const float*)d_in[3];
    const float* W1   = (const float*)d_in[4];
    const float* b1   = (const float*)d_in[5];
    const float* Wc2  = (const float*)d_in[6];
    const float* W2   = (const float*)d_in[7];
    const float* b2   = (const float*)d_in[8];
    float* out = (float*)d_out;

    const int a = in_sizes[0] / KDIM;   // 8192
    const int b = in_sizes[1] / KDIM;   // 8192

    cudaFuncSetAttribute(k_proj_mma, cudaFuncAttributeMaxDynamicSharedMemorySize, SMEM_DYN);

    k_init<<<(2 * KDIM + 255) / 256, 256>>>(out, out_size);

    {
        dim3 gc(KDIM / 8, 2);
        k_cvec<<<gc, 256>>>(Wc1, Wc2, b1, b2, ctx);
    }

    k_tobf16_all<<<2048, 256>>>((const float4*)seq1, (const float4*)seq2,
                                (const float4*)W1, (const float4*)W2);

    {
        dim3 g(KDIM / BN, a / BM, 2);
        k_proj_mma<<<g, 256, SMEM_DYN>>>();
    }

    {
        dim3 gm((a + 7) / 8, 2);
        k_matvec<<<gm, 256>>>(a);
    }

    k_softmax<<<2, 1024>>>(a);

    {
        const int RPB = 32;
        dim3 gp(1, a / RPB, 2);
        k_pool<<<gp, 256>>>(seq1, seq2, out, RPB);
    }
}

// round 10
// speedup vs baseline: 1.1337x; 1.0238x over previous
#include <cuda_runtime.h>
#include <cuda_bf16.h>
#include <math.h>
#include <stdint.h>

// ---------------------------------------------------------------------------
// Problem dims (fixed): a=b=8192, e1=e2=c=m=1024
constexpr int KDIM = 1024;
constexpr int A_MAX = 8192;

constexpr int BM = 128;
constexpr int BN = 128;
constexpr int KC = 64;                  // K chunk (bf16): 128 B per row
constexpr int NCHUNK = KDIM / KC;       // 16
constexpr int TILE_B = BM * 128;        // 16384 B per tile (128B rows)
constexpr int STAGE_B = 2 * TILE_B;     // A + B per stage = 32768
constexpr int NSTAGE = 3;
constexpr int SMEM_DYN = NSTAGE * STAGE_B;  // 98304 B per CTA (2 CTAs = 192KB)

// ---------------------------------------------------------------------------
// Device-global scratch
static __device__ __nv_bfloat16 g_x1[(size_t)A_MAX * KDIM];   // seq1 bf16
static __device__ __nv_bfloat16 g_x2[(size_t)A_MAX * KDIM];   // seq2 bf16
static __device__ __nv_bfloat16 g_wt1[(size_t)KDIM * KDIM];   // W1 bf16
static __device__ __nv_bfloat16 g_wt2[(size_t)KDIM * KDIM];   // W2 bf16
static __device__ __nv_bfloat16 g_p1[(size_t)A_MAX * KDIM];
static __device__ __nv_bfloat16 g_p2[(size_t)A_MAX * KDIM];
static __device__ float g_cvec[2 * KDIM];
static __device__ float g_s[2 * KDIM];
static __device__ float g_logits[2 * A_MAX];
static __device__ float g_w[2 * A_MAX];

// ---------------------------------------------------------------------------
__device__ __forceinline__ uint32_t smem_u32(const void* p) {
    uint32_t a;
    asm("{ .reg .u64 t; cvta.to.shared.u64 t, %1; cvt.u32.u64 %0, t; }" : "=r"(a) : "l"(p));
    return a;
}
__device__ __forceinline__ void cp16(uint32_t smem, const void* g) {
    asm volatile("cp.async.cg.shared.global [%0], [%1], 16;" :: "r"(smem), "l"(g) : "memory");
}
__device__ __forceinline__ void cp_commit() {
    asm volatile("cp.async.commit_group;" ::: "memory");
}
template <int N>
__device__ __forceinline__ void cp_wait() {
    asm volatile("cp.async.wait_group %0;" :: "n"(N) : "memory");
}
__device__ __forceinline__ void ldsm_x4(uint32_t addr, uint32_t* r) {
    asm volatile("ldmatrix.sync.aligned.m8n8.x4.shared.b16 {%0,%1,%2,%3}, [%4];"
                 : "=r"(r[0]), "=r"(r[1]), "=r"(r[2]), "=r"(r[3]) : "r"(addr));
}
__device__ __forceinline__ void mma16816(float* d, const uint32_t* a, const uint32_t* b) {
    asm volatile(
        "mma.sync.aligned.m16n8k16.row.col.f32.bf16.bf16.f32 "
        "{%0,%1,%2,%3}, {%4,%5,%6,%7}, {%8,%9}, {%0,%1,%2,%3};\n"
        : "+f"(d[0]), "+f"(d[1]), "+f"(d[2]), "+f"(d[3])
        : "r"(a[0]), "r"(a[1]), "r"(a[2]), "r"(a[3]), "r"(b[0]), "r"(b[1]));
}

// ---------------------------------------------------------------------------
// Fused prep: blocks [0, 256) do cvec (+ zeroing of g_s/out); blocks [256, ...)
// grid-stride convert seq1/seq2/W1/W2 fp32 -> bf16.
constexpr int NSEQ8 = A_MAX * KDIM / 8;     // 1048576 (8-elem units)
constexpr int NW8   = KDIM * KDIM / 8;      // 131072
constexpr int NCONV = 2 * NSEQ8 + 2 * NW8;  // 2359296 8-elem units
constexpr int CVEC_BLOCKS = 256;            // 128 per branch
constexpr int CONV_BLOCKS = 2048;

__global__ void k_prep(const float4* __restrict__ s1, const float4* __restrict__ s2,
                       const float4* __restrict__ w1x, const float4* __restrict__ w2x,
                       const float* __restrict__ Wc1x, const float* __restrict__ Wc2x,
                       const float* __restrict__ b1x, const float* __restrict__ b2x,
                       const float* __restrict__ ctx,
                       float* __restrict__ out, int out_n) {
    const int bid = blockIdx.x;
    const int tid = threadIdx.x;

    if (bid < CVEC_BLOCKS) {
        // zeroing by blocks 0 and 1
        if (bid == 0) { for (int i = tid; i < 2 * KDIM; i += 256) g_s[i] = 0.f; }
        if (bid == 1) { for (int i = tid; i < out_n; i += 256) out[i] = 0.f; }

        const int which = bid >> 7;              // 0 or 1
        const int blk   = bid & 127;
        const float* Wc = which ? Wc2x : Wc1x;
        const float* bias = which ? b2x : b1x;
        int warp = blk * 8 + (tid >> 5);         // output row 0..1023
        int lane = tid & 31;
        const float4* wrow = (const float4*)(Wc + (size_t)warp * KDIM);
        const float4* c4   = (const float4*)ctx;
        float sum = 0.f;
#pragma unroll
        for (int it = 0; it < KDIM / 128; ++it) {
            float4 wv = wrow[lane + it * 32];
            float4 cv = c4[lane + it * 32];
            sum += wv.x * cv.x + wv.y * cv.y + wv.z * cv.z + wv.w * cv.w;
        }
#pragma unroll
        for (int o = 16; o; o >>= 1) sum += __shfl_xor_sync(0xffffffffu, sum, o);
        if (lane == 0) g_cvec[which * KDIM + warp] = sum + bias[warp];
        return;
    }

    // conversion: 16 elems (two 8-elem units) per thread per step
    const int stride = CONV_BLOCKS * 256;
    for (int u = (bid - CVEC_BLOCKS) * 256 + tid; u < NCONV / 2; u += stride) {
        int i = 2 * u;
        const float4* src;
        uint4* dst;
        int off;
        if (i < NSEQ8)                 { src = s1;  dst = (uint4*)g_x1;  off = i; }
        else if (i < 2 * NSEQ8)        { src = s2;  dst = (uint4*)g_x2;  off = i - NSEQ8; }
        else if (i < 2 * NSEQ8 + NW8)  { src = w1x; dst = (uint4*)g_wt1; off = i - 2 * NSEQ8; }
        else                           { src = w2x; dst = (uint4*)g_wt2; off = i - 2 * NSEQ8 - NW8; }
        float4 v0 = src[2 * off + 0], v1 = src[2 * off + 1];
        float4 v2 = src[2 * off + 2], v3 = src[2 * off + 3];
        uint4 o0, o1;
        __nv_bfloat162 t;
        t = __floats2bfloat162_rn(v0.x, v0.y); o0.x = *(uint32_t*)&t;
        t = __floats2bfloat162_rn(v0.z, v0.w); o0.y = *(uint32_t*)&t;
        t = __floats2bfloat162_rn(v1.x, v1.y); o0.z = *(uint32_t*)&t;
        t = __floats2bfloat162_rn(v1.z, v1.w); o0.w = *(uint32_t*)&t;
        t = __floats2bfloat162_rn(v2.x, v2.y); o1.x = *(uint32_t*)&t;
        t = __floats2bfloat162_rn(v2.z, v2.w); o1.y = *(uint32_t*)&t;
        t = __floats2bfloat162_rn(v3.x, v3.y); o1.z = *(uint32_t*)&t;
        t = __floats2bfloat162_rn(v3.z, v3.w); o1.w = *(uint32_t*)&t;
        dst[off + 0] = o0;
        dst[off + 1] = o1;
    }
}

// ---------------------------------------------------------------------------
// P = elu(X @ Wt.T + cvec). bf16 inputs, cp.async 3-stage pipeline with
// copy-before-MMA ordering (2 chunk-copies in flight during every MMA phase).
// 256 threads = 8 warps (2x4 grid, 64x32 per warp), 2 CTAs/SM.
__global__ __launch_bounds__(256, 2)
void k_proj_mma() {
    extern __shared__ char dynsm[];
    const uint32_t sb = smem_u32(dynsm);

    const int which = blockIdx.z;
    const __nv_bfloat16* __restrict__ X  = which ? g_x2  : g_x1;
    const __nv_bfloat16* __restrict__ Wt = which ? g_wt2 : g_wt1;
    __nv_bfloat16* __restrict__ P = which ? g_p2 : g_p1;
    const float* __restrict__ cvec = g_cvec + which * KDIM;
    float* __restrict__ scol = g_s + which * KDIM;

    const int tid  = threadIdx.x;
    const int wid  = tid >> 5;
    const int lane = tid & 31;
    const int warpRow = wid & 1;
    const int warpCol = wid >> 1;
    const int rowBase = blockIdx.y * BM;
    const int colBase = blockIdx.x * BN;

    const int cprow = tid >> 3;
    const int cpcol = tid & 7;
    const uint32_t cpswz = (uint32_t)((cpcol ^ (cprow & 7)) << 4);
    const __nv_bfloat16* gA = X  + (size_t)(rowBase + cprow) * KDIM + cpcol * 8;
    const __nv_bfloat16* gB = Wt + (size_t)(colBase + cprow) * KDIM + cpcol * 8;

    const int laneQ = lane & 7;
    const int blkId = lane >> 3;
    const uint32_t aKc0 = (uint32_t)(blkId >> 1);
    const uint32_t bKc0 = (uint32_t)(blkId & 1);
    uint32_t aRowOff[4], bRowOff[2];
#pragma unroll
    for (int rb = 0; rb < 4; ++rb)
        aRowOff[rb] = (uint32_t)(warpRow * 64 + rb * 16 + (blkId & 1) * 8 + laneQ) * 128u;
#pragma unroll
    for (int pr = 0; pr < 2; ++pr)
        bRowOff[pr] = (uint32_t)(warpCol * 32 + pr * 16 + (blkId >> 1) * 8 + laneQ) * 128u;

    float acc[4][4][4] = {};

    auto issue = [&](int s, int c) {
        const uint32_t stg = sb + (uint32_t)s * STAGE_B;
        const int ko = c * KC;
#pragma unroll
        for (int it = 0; it < 4; ++it) {
            uint32_t soff = (uint32_t)(cprow + 32 * it) * 128u + cpswz;
            cp16(stg + soff,          gA + (size_t)(32 * it) * KDIM + ko);
            cp16(stg + TILE_B + soff, gB + (size_t)(32 * it) * KDIM + ko);
        }
        cp_commit();
    };

    issue(0, 0);
    issue(1, 1);

    int stage = 0;      // consuming stage
    int wstage = 2;     // next stage to fill
    for (int c = 0; c < NCHUNK; ++c) {
        if (c == NCHUNK - 1) cp_wait<0>(); else cp_wait<1>();
        __syncthreads();

        // issue chunk c+2 BEFORE MMAs: keeps 2 copies in flight during MMA phase
        if (c + 2 < NCHUNK) {
            issue(wstage, c + 2);
            wstage = (wstage == 2) ? 0 : wstage + 1;
        }

        const uint32_t smA = sb + (uint32_t)stage * STAGE_B;
        const uint32_t smB = smA + TILE_B;
#pragma unroll
        for (int ks = 0; ks < 4; ++ks) {
            uint32_t af[4][4], bf[2][4];
            const uint32_t aSw = (uint32_t)(((ks * 2 + aKc0) ^ laneQ) << 4);
            const uint32_t bSw = (uint32_t)(((ks * 2 + bKc0) ^ laneQ) << 4);
#pragma unroll
            for (int rb = 0; rb < 4; ++rb)
                ldsm_x4(smA + aRowOff[rb] + aSw, af[rb]);
#pragma unroll
            for (int pr = 0; pr < 2; ++pr)
                ldsm_x4(smB + bRowOff[pr] + bSw, bf[pr]);
#pragma unroll
            for (int cf = 0; cf < 4; ++cf) {
                const uint32_t* bp = &bf[cf >> 1][(cf & 1) * 2];
#pragma unroll
                for (int rb = 0; rb < 4; ++rb)
                    mma16816(acc[rb][cf], af[rb], bp);
            }
        }

        stage = (stage == 2) ? 0 : stage + 1;
    }

    // ---- epilogue: +cvec, ELU, bf16 store, column sums ----
    const int gq  = lane >> 2;
    const int tig = lane & 3;
    float csum[8];
#pragma unroll
    for (int j = 0; j < 8; ++j) csum[j] = 0.f;

#pragma unroll
    for (int rb = 0; rb < 4; ++rb) {
#pragma unroll
        for (int cf = 0; cf < 4; ++cf) {
            const int col = colBase + warpCol * 32 + cf * 8 + tig * 2;
            const float cv0 = cvec[col], cv1 = cvec[col + 1];
#pragma unroll
            for (int half = 0; half < 2; ++half) {
                const int row = rowBase + warpRow * 64 + rb * 16 + gq + half * 8;
                float v0 = acc[rb][cf][half * 2 + 0] + cv0;
                float v1 = acc[rb][cf][half * 2 + 1] + cv1;
                v0 = (v0 > 0.f) ? v0 : expm1f(v0);
                v1 = (v1 > 0.f) ? v1 : expm1f(v1);
                __nv_bfloat162 pk = __floats2bfloat162_rn(v0, v1);
                *(__nv_bfloat162*)(P + (size_t)row * KDIM + col) = pk;
                csum[cf * 2 + 0] += v0;
                csum[cf * 2 + 1] += v1;
            }
        }
    }
#pragma unroll
    for (int j = 0; j < 8; ++j) {
        float v = csum[j];
        v += __shfl_xor_sync(0xffffffffu, v, 4);
        v += __shfl_xor_sync(0xffffffffu, v, 8);
        v += __shfl_xor_sync(0xffffffffu, v, 16);
        if (gq == 0) {
            int col = colBase + warpCol * 32 + (j >> 1) * 8 + tig * 2 + (j & 1);
            atomicAdd(&scol[col], v);
        }
    }
}

// ---------------------------------------------------------------------------
// logits[z][i] = dot(P[z][i,:], g_s[1-z])  (one warp per row; blockIdx.y = z)
__global__ void k_matvec(int M) {
    int warp = (blockIdx.x * blockDim.x + threadIdx.x) >> 5;
    int lane = threadIdx.x & 31;
    if (warp >= M) return;
    const int z = blockIdx.y;
    const __nv_bfloat16* P = z ? g_p2 : g_p1;
    const uint4* pr = (const uint4*)(P + (size_t)warp * KDIM);
    const float4* s4 = (const float4*)(g_s + (1 - z) * KDIM);
    float sum = 0.f;
#pragma unroll
    for (int it = 0; it < KDIM / 256; ++it) {
        uint4 pk = pr[lane + it * 32];
        float4 sa = s4[(lane + it * 32) * 2 + 0];
        float4 sbv = s4[(lane + it * 32) * 2 + 1];
        float2 p0 = __bfloat1622float2(*(const __nv_bfloat162*)&pk.x);
        float2 p1 = __bfloat1622float2(*(const __nv_bfloat162*)&pk.y);
        float2 p2 = __bfloat1622float2(*(const __nv_bfloat162*)&pk.z);
        float2 p3 = __bfloat1622float2(*(const __nv_bfloat162*)&pk.w);
        sum += p0.x * sa.x + p0.y * sa.y + p1.x * sa.z + p1.y * sa.w;
        sum += p2.x * sbv.x + p2.y * sbv.y + p3.x * sbv.z + p3.y * sbv.w;
    }
#pragma unroll
    for (int o = 16; o; o >>= 1) sum += __shfl_xor_sync(0xffffffffu, sum, o);
    if (lane == 0) g_logits[z * A_MAX + warp] = sum;
}

// softmax over n logits; blockIdx.x = which
__global__ void k_softmax(int n) {
    __shared__ float sbuf[1024];
    const int which = blockIdx.x;
    const float* logits = g_logits + which * A_MAX;
    float* w = g_w + which * A_MAX;
    int tid = threadIdx.x;

    float mx = -3.4e38f;
    for (int i = tid; i < n; i += 1024) mx = fmaxf(mx, logits[i]);
    sbuf[tid] = mx; __syncthreads();
    for (int o = 512; o; o >>= 1) {
        if (tid < o) sbuf[tid] = fmaxf(sbuf[tid], sbuf[tid + o]);
        __syncthreads();
    }
    mx = sbuf[0]; __syncthreads();

    float se = 0.f;
    for (int i = tid; i < n; i += 1024) se += expf(logits[i] - mx);
    sbuf[tid] = se; __syncthreads();
    for (int o = 512; o; o >>= 1) {
        if (tid < o) sbuf[tid] += sbuf[tid + o];
        __syncthreads();
    }
    float inv = 1.f / sbuf[0];

    for (int i = tid; i < n; i += 1024) w[i] = expf(logits[i] - mx) * inv;
}

// out[z*KDIM + col4] += sum_r w[z][r] * seq_z[r, col4]; float4 per thread
__global__ void k_pool(const float* __restrict__ seq1, const float* __restrict__ seq2,
                       float* __restrict__ out, int rowsPerBlock) {
    const int z = blockIdx.z;
    const float* seq = z ? seq2 : seq1;
    const float* w = g_w + z * A_MAX;
    const int c4 = threadIdx.x;
    const int r0 = blockIdx.y * rowsPerBlock;
    float4 acc = {0.f, 0.f, 0.f, 0.f};
    for (int r = r0; r < r0 + rowsPerBlock; ++r) {
        float wr = w[r];
        float4 v = *(const float4*)(seq + (size_t)r * KDIM + c4 * 4);
        acc.x += wr * v.x; acc.y += wr * v.y; acc.z += wr * v.z; acc.w += wr * v.w;
    }
    float* o = out + z * KDIM + c4 * 4;
    atomicAdd(o + 0, acc.x);
    atomicAdd(o + 1, acc.y);
    atomicAdd(o + 2, acc.z);
    atomicAdd(o + 3, acc.w);
}

// ---------------------------------------------------------------------------
extern "C" void kernel_launch(void* const* d_in, const int* in_sizes, int n_in,
                              void* d_out, int out_size) {
    const float* seq1 = (const float*)d_in[0];
    const float* seq2 = (const float*)d_in[1];
    const float* ctx  = (const float*)d_in[2];
    const float* Wc1  = (const float*)d_in[3];
    const float* W1   = (const float*)d_in[4];
    const float* b1   = (const float*)d_in[5];
    const float* Wc2  = (const float*)d_in[6];
    const float* W2   = (const float*)d_in[7];
    const float* b2   = (const float*)d_in[8];
    float* out = (float*)d_out;

    const int a = in_sizes[0] / KDIM;   // 8192
    const int b = in_sizes[1] / KDIM;   // 8192

    cudaFuncSetAttribute(k_proj_mma, cudaFuncAttributeMaxDynamicSharedMemorySize, SMEM_DYN);

    k_prep<<<CVEC_BLOCKS + CONV_BLOCKS, 256>>>(
        (const float4*)seq1, (const float4*)seq2, (const float4*)W1, (const float4*)W2,
        Wc1, Wc2, b1, b2, ctx, out, out_size);

    {
        dim3 g(KDIM / BN, a / BM, 2);
        k_proj_mma<<<g, 256, SMEM_DYN>>>();
    }

    {
        dim3 gm((a + 7) / 8, 2);
        k_matvec<<<gm, 256>>>(a);
    }

    k_softmax<<<2, 1024>>>(a);

    {
        const int RPB = 32;
        dim3 gp(1, a / RPB, 2);
        k_pool<<<gp, 256>>>(seq1, seq2, out, RPB);
    }
}

// round 11
// speedup vs baseline: 1.1757x; 1.0370x over previous
#include <cuda_runtime.h>
#include <cuda_bf16.h>
#include <math.h>
#include <stdint.h>

// ---------------------------------------------------------------------------
// Problem dims (fixed): a=b=8192, e1=e2=c=m=1024
constexpr int KDIM = 1024;
constexpr int A_MAX = 8192;

constexpr int BM = 128;
constexpr int BN = 128;
constexpr int KC = 64;                  // K chunk (bf16): 128 B per row
constexpr int NCHUNK = KDIM / KC;       // 16
constexpr int TILE_B = BM * 128;        // 16384 B per tile (128B rows)
constexpr int STAGE_B = 2 * TILE_B;     // A + B per stage = 32768
constexpr int NSTAGE = 3;
constexpr int SMEM_DYN = NSTAGE * STAGE_B;  // 98304 B per CTA (2 CTAs = 192KB)

// ---------------------------------------------------------------------------
// Device-global scratch
static __device__ __nv_bfloat16 g_x1[(size_t)A_MAX * KDIM];
static __device__ __nv_bfloat16 g_x2[(size_t)A_MAX * KDIM];
static __device__ __nv_bfloat16 g_wt1[(size_t)KDIM * KDIM];
static __device__ __nv_bfloat16 g_wt2[(size_t)KDIM * KDIM];
static __device__ __nv_bfloat16 g_p1[(size_t)A_MAX * KDIM];
static __device__ __nv_bfloat16 g_p2[(size_t)A_MAX * KDIM];
static __device__ float g_cvec[2 * KDIM];
static __device__ float g_s[2 * KDIM];
static __device__ float g_logits[2 * A_MAX];
static __device__ unsigned g_mx[2];      // ordered-key float max
static __device__ float g_mxf[2];        // max as float (set by k_sumexp)
static __device__ float g_inv[2];        // 1/sum(exp)

// ordered-uint key for float max atomics (monotone in x)
__device__ __forceinline__ unsigned fkey(float x) {
    unsigned u = __float_as_uint(x);
    return (u & 0x80000000u) ? ~u : (u | 0x80000000u);
}
__device__ __forceinline__ float fkey_inv(unsigned k) {
    return (k & 0x80000000u) ? __uint_as_float(k ^ 0x80000000u) : __uint_as_float(~k);
}
constexpr unsigned FKEY_NEG_MAX = 0x00800000u;   // fkey(-FLT_MAX)

// ---------------------------------------------------------------------------
__device__ __forceinline__ uint32_t smem_u32(const void* p) {
    uint32_t a;
    asm("{ .reg .u64 t; cvta.to.shared.u64 t, %1; cvt.u32.u64 %0, t; }" : "=r"(a) : "l"(p));
    return a;
}
__device__ __forceinline__ void cp16(uint32_t smem, const void* g) {
    asm volatile("cp.async.cg.shared.global [%0], [%1], 16;" :: "r"(smem), "l"(g) : "memory");
}
__device__ __forceinline__ void cp_commit() {
    asm volatile("cp.async.commit_group;" ::: "memory");
}
template <int N>
__device__ __forceinline__ void cp_wait() {
    asm volatile("cp.async.wait_group %0;" :: "n"(N) : "memory");
}
__device__ __forceinline__ void ldsm_x4(uint32_t addr, uint32_t* r) {
    asm volatile("ldmatrix.sync.aligned.m8n8.x4.shared.b16 {%0,%1,%2,%3}, [%4];"
                 : "=r"(r[0]), "=r"(r[1]), "=r"(r[2]), "=r"(r[3]) : "r"(addr));
}
__device__ __forceinline__ void mma16816(float* d, const uint32_t* a, const uint32_t* b) {
    asm volatile(
        "mma.sync.aligned.m16n8k16.row.col.f32.bf16.bf16.f32 "
        "{%0,%1,%2,%3}, {%4,%5,%6,%7}, {%8,%9}, {%0,%1,%2,%3};\n"
        : "+f"(d[0]), "+f"(d[1]), "+f"(d[2]), "+f"(d[3])
        : "r"(a[0]), "r"(a[1]), "r"(a[2]), "r"(a[3]), "r"(b[0]), "r"(b[1]));
}

// ---------------------------------------------------------------------------
// Fused prep: blocks [0, 256) do cvec (+ zero/init); blocks [256, ...) convert.
constexpr int NSEQ8 = A_MAX * KDIM / 8;
constexpr int NW8   = KDIM * KDIM / 8;
constexpr int NCONV = 2 * NSEQ8 + 2 * NW8;
constexpr int CVEC_BLOCKS = 256;
constexpr int CONV_BLOCKS = 2048;

__global__ void k_prep(const float4* __restrict__ s1, const float4* __restrict__ s2,
                       const float4* __restrict__ w1x, const float4* __restrict__ w2x,
                       const float* __restrict__ Wc1x, const float* __restrict__ Wc2x,
                       const float* __restrict__ b1x, const float* __restrict__ b2x,
                       const float* __restrict__ ctx,
                       float* __restrict__ out, int out_n) {
    const int bid = blockIdx.x;
    const int tid = threadIdx.x;

    if (bid < CVEC_BLOCKS) {
        if (bid == 0) {
            for (int i = tid; i < 2 * KDIM; i += 256) g_s[i] = 0.f;
            if (tid < 2) g_mx[tid] = FKEY_NEG_MAX;
        }
        if (bid == 1) { for (int i = tid; i < out_n; i += 256) out[i] = 0.f; }

        const int which = bid >> 7;
        const int blk   = bid & 127;
        const float* Wc = which ? Wc2x : Wc1x;
        const float* bias = which ? b2x : b1x;
        int warp = blk * 8 + (tid >> 5);
        int lane = tid & 31;
        const float4* wrow = (const float4*)(Wc + (size_t)warp * KDIM);
        const float4* c4   = (const float4*)ctx;
        float sum = 0.f;
#pragma unroll
        for (int it = 0; it < KDIM / 128; ++it) {
            float4 wv = wrow[lane + it * 32];
            float4 cv = c4[lane + it * 32];
            sum += wv.x * cv.x + wv.y * cv.y + wv.z * cv.z + wv.w * cv.w;
        }
#pragma unroll
        for (int o = 16; o; o >>= 1) sum += __shfl_xor_sync(0xffffffffu, sum, o);
        if (lane == 0) g_cvec[which * KDIM + warp] = sum + bias[warp];
        return;
    }

    const int stride = CONV_BLOCKS * 256;
    for (int u = (bid - CVEC_BLOCKS) * 256 + tid; u < NCONV / 2; u += stride) {
        int i = 2 * u;
        const float4* src;
        uint4* dst;
        int off;
        if (i < NSEQ8)                 { src = s1;  dst = (uint4*)g_x1;  off = i; }
        else if (i < 2 * NSEQ8)        { src = s2;  dst = (uint4*)g_x2;  off = i - NSEQ8; }
        else if (i < 2 * NSEQ8 + NW8)  { src = w1x; dst = (uint4*)g_wt1; off = i - 2 * NSEQ8; }
        else                           { src = w2x; dst = (uint4*)g_wt2; off = i - 2 * NSEQ8 - NW8; }
        float4 v0 = src[2 * off + 0], v1 = src[2 * off + 1];
        float4 v2 = src[2 * off + 2], v3 = src[2 * off + 3];
        uint4 o0, o1;
        __nv_bfloat162 t;
        t = __floats2bfloat162_rn(v0.x, v0.y); o0.x = *(uint32_t*)&t;
        t = __floats2bfloat162_rn(v0.z, v0.w); o0.y = *(uint32_t*)&t;
        t = __floats2bfloat162_rn(v1.x, v1.y); o0.z = *(uint32_t*)&t;
        t = __floats2bfloat162_rn(v1.z, v1.w); o0.w = *(uint32_t*)&t;
        t = __floats2bfloat162_rn(v2.x, v2.y); o1.x = *(uint32_t*)&t;
        t = __floats2bfloat162_rn(v2.z, v2.w); o1.y = *(uint32_t*)&t;
        t = __floats2bfloat162_rn(v3.x, v3.y); o1.z = *(uint32_t*)&t;
        t = __floats2bfloat162_rn(v3.z, v3.w); o1.w = *(uint32_t*)&t;
        dst[off + 0] = o0;
        dst[off + 1] = o1;
    }
}

// ---------------------------------------------------------------------------
// P = elu(X @ Wt.T + cvec). bf16 inputs, cp.async 3-stage pipeline,
// copy-before-MMA ordering. 256 threads = 8 warps (2x4, 64x32/warp), 2 CTAs/SM.
__global__ __launch_bounds__(256, 2)
void k_proj_mma() {
    extern __shared__ char dynsm[];
    const uint32_t sb = smem_u32(dynsm);

    const int which = blockIdx.z;
    const __nv_bfloat16* __restrict__ X  = which ? g_x2  : g_x1;
    const __nv_bfloat16* __restrict__ Wt = which ? g_wt2 : g_wt1;
    __nv_bfloat16* __restrict__ P = which ? g_p2 : g_p1;
    const float* __restrict__ cvec = g_cvec + which * KDIM;
    float* __restrict__ scol = g_s + which * KDIM;

    const int tid  = threadIdx.x;
    const int wid  = tid >> 5;
    const int lane = tid & 31;
    const int warpRow = wid & 1;
    const int warpCol = wid >> 1;
    const int rowBase = blockIdx.y * BM;
    const int colBase = blockIdx.x * BN;

    const int cprow = tid >> 3;
    const int cpcol = tid & 7;
    const uint32_t cpswz = (uint32_t)((cpcol ^ (cprow & 7)) << 4);
    const __nv_bfloat16* gA = X  + (size_t)(rowBase + cprow) * KDIM + cpcol * 8;
    const __nv_bfloat16* gB = Wt + (size_t)(colBase + cprow) * KDIM + cpcol * 8;

    const int laneQ = lane & 7;
    const int blkId = lane >> 3;
    const uint32_t aKc0 = (uint32_t)(blkId >> 1);
    const uint32_t bKc0 = (uint32_t)(blkId & 1);
    uint32_t aRowOff[4], bRowOff[2];
#pragma unroll
    for (int rb = 0; rb < 4; ++rb)
        aRowOff[rb] = (uint32_t)(warpRow * 64 + rb * 16 + (blkId & 1) * 8 + laneQ) * 128u;
#pragma unroll
    for (int pr = 0; pr < 2; ++pr)
        bRowOff[pr] = (uint32_t)(warpCol * 32 + pr * 16 + (blkId >> 1) * 8 + laneQ) * 128u;

    // precomputed per-ks swizzle offsets (hoists XOR/shift out of mainloop)
    uint32_t aSwT[4], bSwT[4];
#pragma unroll
    for (int ks = 0; ks < 4; ++ks) {
        aSwT[ks] = (uint32_t)((((uint32_t)(ks * 2) + aKc0) ^ (uint32_t)laneQ) << 4);
        bSwT[ks] = (uint32_t)((((uint32_t)(ks * 2) + bKc0) ^ (uint32_t)laneQ) << 4);
    }

    float acc[4][4][4] = {};

    auto issue = [&](int s, int c) {
        const uint32_t stg = sb + (uint32_t)s * STAGE_B;
        const int ko = c * KC;
#pragma unroll
        for (int it = 0; it < 4; ++it) {
            uint32_t soff = (uint32_t)(cprow + 32 * it) * 128u + cpswz;
            cp16(stg + soff,          gA + (size_t)(32 * it) * KDIM + ko);
            cp16(stg + TILE_B + soff, gB + (size_t)(32 * it) * KDIM + ko);
        }
        cp_commit();
    };

    issue(0, 0);
    issue(1, 1);

    int stage = 0;
    int wstage = 2;
    for (int c = 0; c < NCHUNK; ++c) {
        if (c == NCHUNK - 1) cp_wait<0>(); else cp_wait<1>();
        __syncthreads();

        if (c + 2 < NCHUNK) {
            issue(wstage, c + 2);
            wstage = (wstage == 2) ? 0 : wstage + 1;
        }

        const uint32_t smA = sb + (uint32_t)stage * STAGE_B;
        const uint32_t smB = smA + TILE_B;
#pragma unroll
        for (int ks = 0; ks < 4; ++ks) {
            uint32_t af[4][4], bf[2][4];
#pragma unroll
            for (int rb = 0; rb < 4; ++rb)
                ldsm_x4(smA + aRowOff[rb] + aSwT[ks], af[rb]);
#pragma unroll
            for (int pr = 0; pr < 2; ++pr)
                ldsm_x4(smB + bRowOff[pr] + bSwT[ks], bf[pr]);
#pragma unroll
            for (int cf = 0; cf < 4; ++cf) {
                const uint32_t* bp = &bf[cf >> 1][(cf & 1) * 2];
#pragma unroll
                for (int rb = 0; rb < 4; ++rb)
                    mma16816(acc[rb][cf], af[rb], bp);
            }
        }

        stage = (stage == 2) ? 0 : stage + 1;
    }

    // ---- epilogue: +cvec, ELU, bf16 store, column sums ----
    const int gq  = lane >> 2;
    const int tig = lane & 3;
    float csum[8];
#pragma unroll
    for (int j = 0; j < 8; ++j) csum[j] = 0.f;

#pragma unroll
    for (int rb = 0; rb < 4; ++rb) {
#pragma unroll
        for (int cf = 0; cf < 4; ++cf) {
            const int col = colBase + warpCol * 32 + cf * 8 + tig * 2;
            const float cv0 = cvec[col], cv1 = cvec[col + 1];
#pragma unroll
            for (int half = 0; half < 2; ++half) {
                const int row = rowBase + warpRow * 64 + rb * 16 + gq + half * 8;
                float v0 = acc[rb][cf][half * 2 + 0] + cv0;
                float v1 = acc[rb][cf][half * 2 + 1] + cv1;
                v0 = (v0 > 0.f) ? v0 : expm1f(v0);
                v1 = (v1 > 0.f) ? v1 : expm1f(v1);
                __nv_bfloat162 pk = __floats2bfloat162_rn(v0, v1);
                *(__nv_bfloat162*)(P + (size_t)row * KDIM + col) = pk;
                csum[cf * 2 + 0] += v0;
                csum[cf * 2 + 1] += v1;
            }
        }
    }
#pragma unroll
    for (int j = 0; j < 8; ++j) {
        float v = csum[j];
        v += __shfl_xor_sync(0xffffffffu, v, 4);
        v += __shfl_xor_sync(0xffffffffu, v, 8);
        v += __shfl_xor_sync(0xffffffffu, v, 16);
        if (gq == 0) {
            int col = colBase + warpCol * 32 + (j >> 1) * 8 + tig * 2 + (j & 1);
            atomicAdd(&scol[col], v);
        }
    }
}

// ---------------------------------------------------------------------------
// logits[z][i] = dot(P[z][i,:], g_s[1-z]); also merges block max into g_mx[z].
__global__ void k_matvec(int M) {
    __shared__ float smax[8];
    int warp = (blockIdx.x * blockDim.x + threadIdx.x) >> 5;
    int wloc = threadIdx.x >> 5;
    int lane = threadIdx.x & 31;
    const int z = blockIdx.y;
    const __nv_bfloat16* P = z ? g_p2 : g_p1;
    const uint4* pr = (const uint4*)(P + (size_t)warp * KDIM);
    const float4* s4 = (const float4*)(g_s + (1 - z) * KDIM);
    float sum = 0.f;
#pragma unroll
    for (int it = 0; it < KDIM / 256; ++it) {
        uint4 pk = pr[lane + it * 32];
        float4 sa = s4[(lane + it * 32) * 2 + 0];
        float4 sbv = s4[(lane + it * 32) * 2 + 1];
        float2 p0 = __bfloat1622float2(*(const __nv_bfloat162*)&pk.x);
        float2 p1 = __bfloat1622float2(*(const __nv_bfloat162*)&pk.y);
        float2 p2 = __bfloat1622float2(*(const __nv_bfloat162*)&pk.z);
        float2 p3 = __bfloat1622float2(*(const __nv_bfloat162*)&pk.w);
        sum += p0.x * sa.x + p0.y * sa.y + p1.x * sa.z + p1.y * sa.w;
        sum += p2.x * sbv.x + p2.y * sbv.y + p3.x * sbv.z + p3.y * sbv.w;
    }
#pragma unroll
    for (int o = 16; o; o >>= 1) sum += __shfl_xor_sync(0xffffffffu, sum, o);
    if (lane == 0) {
        g_logits[z * A_MAX + warp] = sum;
        smax[wloc] = sum;
    }
    __syncthreads();
    if (threadIdx.x == 0) {
        float m = smax[0];
#pragma unroll
        for (int i = 1; i < 8; ++i) m = fmaxf(m, smax[i]);
        atomicMax(&g_mx[z], fkey(m));
    }
}

// one pass: sum of exp(logits - mx); writes g_mxf and g_inv. blockIdx.x = z.
__global__ void k_sumexp(int n) {
    __shared__ float sred[32];
    const int z = blockIdx.x;
    const int tid = threadIdx.x;
    const float mx = fkey_inv(g_mx[z]);
    const float* logits = g_logits + z * A_MAX;
    float s = 0.f;
    for (int i = tid; i < n; i += 1024) s += expf(logits[i] - mx);
#pragma unroll
    for (int o = 16; o; o >>= 1) s += __shfl_xor_sync(0xffffffffu, s, o);
    if ((tid & 31) == 0) sred[tid >> 5] = s;
    __syncthreads();
    if (tid < 32) {
        float t = sred[tid];
#pragma unroll
        for (int o = 16; o; o >>= 1) t += __shfl_xor_sync(0xffffffffu, t, o);
        if (tid == 0) { g_mxf[z] = mx; g_inv[z] = 1.f / t; }
    }
}

// out[z*KDIM + col4] += sum_r exp(logits[r]-mx)*inv * seq_z[r, col4]
__global__ void k_pool(const float* __restrict__ seq1, const float* __restrict__ seq2,
                       float* __restrict__ out, int rowsPerBlock) {
    __shared__ float wsh[32];
    const int z = blockIdx.z;
    const float* seq = z ? seq2 : seq1;
    const int c4 = threadIdx.x;
    const int r0 = blockIdx.y * rowsPerBlock;
    if (threadIdx.x < 32) {
        float mx = g_mxf[z], inv = g_inv[z];
        wsh[threadIdx.x] = expf(g_logits[z * A_MAX + r0 + threadIdx.x] - mx) * inv;
    }
    __syncthreads();
    float4 acc = {0.f, 0.f, 0.f, 0.f};
    for (int r = 0; r < rowsPerBlock; ++r) {
        float wr = wsh[r];
        float4 v = *(const float4*)(seq + (size_t)(r0 + r) * KDIM + c4 * 4);
        acc.x += wr * v.x; acc.y += wr * v.y; acc.z += wr * v.z; acc.w += wr * v.w;
    }
    float* o = out + z * KDIM + c4 * 4;
    atomicAdd(o + 0, acc.x);
    atomicAdd(o + 1, acc.y);
    atomicAdd(o + 2, acc.z);
    atomicAdd(o + 3, acc.w);
}

// ---------------------------------------------------------------------------
extern "C" void kernel_launch(void* const* d_in, const int* in_sizes, int n_in,
                              void* d_out, int out_size) {
    const float* seq1 = (const float*)d_in[0];
    const float* seq2 = (const float*)d_in[1];
    const float* ctx  = (const float*)d_in[2];
    const float* Wc1  = (const float*)d_in[3];
    const float* W1   = (const float*)d_in[4];
    const float* b1   = (const float*)d_in[5];
    const float* Wc2  = (const float*)d_in[6];
    const float* W2   = (const float*)d_in[7];
    const float* b2   = (const float*)d_in[8];
    float* out = (float*)d_out;

    const int a = in_sizes[0] / KDIM;   // 8192
    const int b = in_sizes[1] / KDIM;   // 8192

    cudaFuncSetAttribute(k_proj_mma, cudaFuncAttributeMaxDynamicSharedMemorySize, SMEM_DYN);

    k_prep<<<CVEC_BLOCKS + CONV_BLOCKS, 256>>>(
        (const float4*)seq1, (const float4*)seq2, (const float4*)W1, (const float4*)W2,
        Wc1, Wc2, b1, b2, ctx, out, out_size);

    {
        dim3 g(KDIM / BN, a / BM, 2);
        k_proj_mma<<<g, 256, SMEM_DYN>>>();
    }

    {
        dim3 gm((a + 7) / 8, 2);
        k_matvec<<<gm, 256>>>(a);
    }

    k_sumexp<<<2, 1024>>>(a);

    {
        const int RPB = 32;
        dim3 gp(1, a / RPB, 2);
        k_pool<<<gp, 256>>>(seq1, seq2, out, RPB);
    }
}

// round 12
// speedup vs baseline: 1.2055x; 1.0253x over previous
#include <cuda_runtime.h>
#include <cuda_bf16.h>
#include <math.h>
#include <stdint.h>

// ---------------------------------------------------------------------------
// Problem dims (fixed): a=b=8192, e1=e2=c=m=1024
constexpr int KDIM = 1024;
constexpr int A_MAX = 8192;

constexpr int BM = 128;
constexpr int BN = 128;
constexpr int KC = 64;                  // K chunk (bf16): 128 B per row
constexpr int NCHUNK = KDIM / KC;       // 16
constexpr int TILE_B = BM * 128;        // 16384 B per tile (128B rows)
constexpr int STAGE_B = 2 * TILE_B;     // A + B per stage = 32768
constexpr int NSTAGE = 3;
constexpr int SMEM_DYN = NSTAGE * STAGE_B;  // 98304 B per CTA (2 CTAs = 192KB)

// ---------------------------------------------------------------------------
// Device-global scratch
static __device__ __nv_bfloat16 g_x1[(size_t)A_MAX * KDIM];
static __device__ __nv_bfloat16 g_x2[(size_t)A_MAX * KDIM];
static __device__ __nv_bfloat16 g_wt1[(size_t)KDIM * KDIM];
static __device__ __nv_bfloat16 g_wt2[(size_t)KDIM * KDIM];
static __device__ __nv_bfloat16 g_p1[(size_t)A_MAX * KDIM];
static __device__ __nv_bfloat16 g_p2[(size_t)A_MAX * KDIM];
static __device__ float g_cvec[2 * KDIM];
static __device__ float g_s[2 * KDIM];
static __device__ float g_logits[2 * A_MAX];
static __device__ unsigned g_mx[2];      // ordered-key float max
static __device__ float g_sum[2];        // sum of exp(l - mx)

// ordered-uint key for float max atomics (monotone in x)
__device__ __forceinline__ unsigned fkey(float x) {
    unsigned u = __float_as_uint(x);
    return (u & 0x80000000u) ? ~u : (u | 0x80000000u);
}
__device__ __forceinline__ float fkey_inv(unsigned k) {
    return (k & 0x80000000u) ? __uint_as_float(k ^ 0x80000000u) : __uint_as_float(~k);
}
constexpr unsigned FKEY_NEG_MAX = 0x00800000u;   // fkey(-FLT_MAX)

// ---------------------------------------------------------------------------
__device__ __forceinline__ uint32_t smem_u32(const void* p) {
    uint32_t a;
    asm("{ .reg .u64 t; cvta.to.shared.u64 t, %1; cvt.u32.u64 %0, t; }" : "=r"(a) : "l"(p));
    return a;
}
__device__ __forceinline__ void cp16(uint32_t smem, const void* g) {
    asm volatile("cp.async.cg.shared.global [%0], [%1], 16;" :: "r"(smem), "l"(g) : "memory");
}
__device__ __forceinline__ void cp_commit() {
    asm volatile("cp.async.commit_group;" ::: "memory");
}
template <int N>
__device__ __forceinline__ void cp_wait() {
    asm volatile("cp.async.wait_group %0;" :: "n"(N) : "memory");
}
__device__ __forceinline__ void ldsm_x4(uint32_t addr, uint32_t* r) {
    asm volatile("ldmatrix.sync.aligned.m8n8.x4.shared.b16 {%0,%1,%2,%3}, [%4];"
                 : "=r"(r[0]), "=r"(r[1]), "=r"(r[2]), "=r"(r[3]) : "r"(addr));
}
__device__ __forceinline__ void mma16816(float* d, const uint32_t* a, const uint32_t* b) {
    asm volatile(
        "mma.sync.aligned.m16n8k16.row.col.f32.bf16.bf16.f32 "
        "{%0,%1,%2,%3}, {%4,%5,%6,%7}, {%8,%9}, {%0,%1,%2,%3};\n"
        : "+f"(d[0]), "+f"(d[1]), "+f"(d[2]), "+f"(d[3])
        : "r"(a[0]), "r"(a[1]), "r"(a[2]), "r"(a[3]), "r"(b[0]), "r"(b[1]));
}

// ---------------------------------------------------------------------------
// Fused prep: blocks [0, 256) do cvec (+ zero/init); blocks [256, ...) convert.
constexpr int NSEQ8 = A_MAX * KDIM / 8;
constexpr int NW8   = KDIM * KDIM / 8;
constexpr int NCONV = 2 * NSEQ8 + 2 * NW8;
constexpr int CVEC_BLOCKS = 256;
constexpr int CONV_BLOCKS = 2048;

__global__ void k_prep(const float4* __restrict__ s1, const float4* __restrict__ s2,
                       const float4* __restrict__ w1x, const float4* __restrict__ w2x,
                       const float* __restrict__ Wc1x, const float* __restrict__ Wc2x,
                       const float* __restrict__ b1x, const float* __restrict__ b2x,
                       const float* __restrict__ ctx,
                       float* __restrict__ out, int out_n) {
    const int bid = blockIdx.x;
    const int tid = threadIdx.x;

    if (bid < CVEC_BLOCKS) {
        if (bid == 0) {
            for (int i = tid; i < 2 * KDIM; i += 256) g_s[i] = 0.f;
            if (tid < 2) { g_mx[tid] = FKEY_NEG_MAX; g_sum[tid] = 0.f; }
        }
        if (bid == 1) { for (int i = tid; i < out_n; i += 256) out[i] = 0.f; }

        const int which = bid >> 7;
        const int blk   = bid & 127;
        const float* Wc = which ? Wc2x : Wc1x;
        const float* bias = which ? b2x : b1x;
        int warp = blk * 8 + (tid >> 5);
        int lane = tid & 31;
        const float4* wrow = (const float4*)(Wc + (size_t)warp * KDIM);
        const float4* c4   = (const float4*)ctx;
        float sum = 0.f;
#pragma unroll
        for (int it = 0; it < KDIM / 128; ++it) {
            float4 wv = wrow[lane + it * 32];
            float4 cv = c4[lane + it * 32];
            sum += wv.x * cv.x + wv.y * cv.y + wv.z * cv.z + wv.w * cv.w;
        }
#pragma unroll
        for (int o = 16; o; o >>= 1) sum += __shfl_xor_sync(0xffffffffu, sum, o);
        if (lane == 0) g_cvec[which * KDIM + warp] = sum + bias[warp];
        return;
    }

    const int stride = CONV_BLOCKS * 256;
    for (int u = (bid - CVEC_BLOCKS) * 256 + tid; u < NCONV / 2; u += stride) {
        int i = 2 * u;
        const float4* src;
        uint4* dst;
        int off;
        if (i < NSEQ8)                 { src = s1;  dst = (uint4*)g_x1;  off = i; }
        else if (i < 2 * NSEQ8)        { src = s2;  dst = (uint4*)g_x2;  off = i - NSEQ8; }
        else if (i < 2 * NSEQ8 + NW8)  { src = w1x; dst = (uint4*)g_wt1; off = i - 2 * NSEQ8; }
        else                           { src = w2x; dst = (uint4*)g_wt2; off = i - 2 * NSEQ8 - NW8; }
        float4 v0 = src[2 * off + 0], v1 = src[2 * off + 1];
        float4 v2 = src[2 * off + 2], v3 = src[2 * off + 3];
        uint4 o0, o1;
        __nv_bfloat162 t;
        t = __floats2bfloat162_rn(v0.x, v0.y); o0.x = *(uint32_t*)&t;
        t = __floats2bfloat162_rn(v0.z, v0.w); o0.y = *(uint32_t*)&t;
        t = __floats2bfloat162_rn(v1.x, v1.y); o0.z = *(uint32_t*)&t;
        t = __floats2bfloat162_rn(v1.z, v1.w); o0.w = *(uint32_t*)&t;
        t = __floats2bfloat162_rn(v2.x, v2.y); o1.x = *(uint32_t*)&t;
        t = __floats2bfloat162_rn(v2.z, v2.w); o1.y = *(uint32_t*)&t;
        t = __floats2bfloat162_rn(v3.x, v3.y); o1.z = *(uint32_t*)&t;
        t = __floats2bfloat162_rn(v3.z, v3.w); o1.w = *(uint32_t*)&t;
        dst[off + 0] = o0;
        dst[off + 1] = o1;
    }
}

// ---------------------------------------------------------------------------
// P = elu(X @ Wt.T + cvec). bf16 inputs, cp.async 3-stage pipeline,
// copy-before-MMA ordering. 256 threads = 8 warps (2x4, 64x32/warp), 2 CTAs/SM.
__global__ __launch_bounds__(256, 2)
void k_proj_mma() {
    extern __shared__ char dynsm[];
    const uint32_t sb = smem_u32(dynsm);

    const int which = blockIdx.z;
    const __nv_bfloat16* __restrict__ X  = which ? g_x2  : g_x1;
    const __nv_bfloat16* __restrict__ Wt = which ? g_wt2 : g_wt1;
    __nv_bfloat16* __restrict__ P = which ? g_p2 : g_p1;
    const float* __restrict__ cvec = g_cvec + which * KDIM;
    float* __restrict__ scol = g_s + which * KDIM;

    const int tid  = threadIdx.x;
    const int wid  = tid >> 5;
    const int lane = tid & 31;
    const int warpRow = wid & 1;
    const int warpCol = wid >> 1;
    const int rowBase = blockIdx.y * BM;
    const int colBase = blockIdx.x * BN;

    const int cprow = tid >> 3;
    const int cpcol = tid & 7;
    const uint32_t cpswz = (uint32_t)((cpcol ^ (cprow & 7)) << 4);
    const __nv_bfloat16* gA = X  + (size_t)(rowBase + cprow) * KDIM + cpcol * 8;
    const __nv_bfloat16* gB = Wt + (size_t)(colBase + cprow) * KDIM + cpcol * 8;

    const int laneQ = lane & 7;
    const int blkId = lane >> 3;
    const uint32_t aKc0 = (uint32_t)(blkId >> 1);
    const uint32_t bKc0 = (uint32_t)(blkId & 1);
    uint32_t aRowOff[4], bRowOff[2];
#pragma unroll
    for (int rb = 0; rb < 4; ++rb)
        aRowOff[rb] = (uint32_t)(warpRow * 64 + rb * 16 + (blkId & 1) * 8 + laneQ) * 128u;
#pragma unroll
    for (int pr = 0; pr < 2; ++pr)
        bRowOff[pr] = (uint32_t)(warpCol * 32 + pr * 16 + (blkId >> 1) * 8 + laneQ) * 128u;

    uint32_t aSwT[4], bSwT[4];
#pragma unroll
    for (int ks = 0; ks < 4; ++ks) {
        aSwT[ks] = (uint32_t)((((uint32_t)(ks * 2) + aKc0) ^ (uint32_t)laneQ) << 4);
        bSwT[ks] = (uint32_t)((((uint32_t)(ks * 2) + bKc0) ^ (uint32_t)laneQ) << 4);
    }

    float acc[4][4][4] = {};

    auto issue = [&](int s, int c) {
        const uint32_t stg = sb + (uint32_t)s * STAGE_B;
        const int ko = c * KC;
#pragma unroll
        for (int it = 0; it < 4; ++it) {
            uint32_t soff = (uint32_t)(cprow + 32 * it) * 128u + cpswz;
            cp16(stg + soff,          gA + (size_t)(32 * it) * KDIM + ko);
            cp16(stg + TILE_B + soff, gB + (size_t)(32 * it) * KDIM + ko);
        }
        cp_commit();
    };

    issue(0, 0);
    issue(1, 1);

    int stage = 0;
    int wstage = 2;
    for (int c = 0; c < NCHUNK; ++c) {
        if (c == NCHUNK - 1) cp_wait<0>(); else cp_wait<1>();
        __syncthreads();

        if (c + 2 < NCHUNK) {
            issue(wstage, c + 2);
            wstage = (wstage == 2) ? 0 : wstage + 1;
        }

        const uint32_t smA = sb + (uint32_t)stage * STAGE_B;
        const uint32_t smB = smA + TILE_B;
#pragma unroll
        for (int ks = 0; ks < 4; ++ks) {
            uint32_t af[4][4], bf[2][4];
#pragma unroll
            for (int rb = 0; rb < 4; ++rb)
                ldsm_x4(smA + aRowOff[rb] + aSwT[ks], af[rb]);
#pragma unroll
            for (int pr = 0; pr < 2; ++pr)
                ldsm_x4(smB + bRowOff[pr] + bSwT[ks], bf[pr]);
#pragma unroll
            for (int cf = 0; cf < 4; ++cf) {
                const uint32_t* bp = &bf[cf >> 1][(cf & 1) * 2];
#pragma unroll
                for (int rb = 0; rb < 4; ++rb)
                    mma16816(acc[rb][cf], af[rb], bp);
            }
        }

        stage = (stage == 2) ? 0 : stage + 1;
    }

    // ---- epilogue: +cvec, ELU, bf16 store, column sums ----
    const int gq  = lane >> 2;
    const int tig = lane & 3;
    float csum[8];
#pragma unroll
    for (int j = 0; j < 8; ++j) csum[j] = 0.f;

#pragma unroll
    for (int rb = 0; rb < 4; ++rb) {
#pragma unroll
        for (int cf = 0; cf < 4; ++cf) {
            const int col = colBase + warpCol * 32 + cf * 8 + tig * 2;
            const float cv0 = cvec[col], cv1 = cvec[col + 1];
#pragma unroll
            for (int half = 0; half < 2; ++half) {
                const int row = rowBase + warpRow * 64 + rb * 16 + gq + half * 8;
                float v0 = acc[rb][cf][half * 2 + 0] + cv0;
                float v1 = acc[rb][cf][half * 2 + 1] + cv1;
                v0 = (v0 > 0.f) ? v0 : expm1f(v0);
                v1 = (v1 > 0.f) ? v1 : expm1f(v1);
                __nv_bfloat162 pk = __floats2bfloat162_rn(v0, v1);
                *(__nv_bfloat162*)(P + (size_t)row * KDIM + col) = pk;
                csum[cf * 2 + 0] += v0;
                csum[cf * 2 + 1] += v1;
            }
        }
    }
#pragma unroll
    for (int j = 0; j < 8; ++j) {
        float v = csum[j];
        v += __shfl_xor_sync(0xffffffffu, v, 4);
        v += __shfl_xor_sync(0xffffffffu, v, 8);
        v += __shfl_xor_sync(0xffffffffu, v, 16);
        if (gq == 0) {
            int col = colBase + warpCol * 32 + (j >> 1) * 8 + tig * 2 + (j & 1);
            atomicAdd(&scol[col], v);
        }
    }
}

// ---------------------------------------------------------------------------
// logits: 2 rows per warp (8 independent 16B loads in flight). Also merges
// block max into g_mx[z]. Grid: (M/16, 2) x 256 threads.
__global__ void k_matvec(int M) {
    __shared__ float smax[8];
    const int gw   = (blockIdx.x * blockDim.x + threadIdx.x) >> 5;
    const int wloc = threadIdx.x >> 5;
    const int lane = threadIdx.x & 31;
    const int z = blockIdx.y;
    const int r0 = gw * 2;
    const __nv_bfloat16* P = z ? g_p2 : g_p1;
    const uint4* pr0 = (const uint4*)(P + (size_t)r0 * KDIM);
    const uint4* pr1 = (const uint4*)(P + (size_t)(r0 + 1) * KDIM);
    const float4* s4 = (const float4*)(g_s + (1 - z) * KDIM);
    float sum0 = 0.f, sum1 = 0.f;
#pragma unroll
    for (int it = 0; it < KDIM / 256; ++it) {
        uint4 pa = pr0[lane + it * 32];
        uint4 pb = pr1[lane + it * 32];
        float4 sa = s4[(lane + it * 32) * 2 + 0];
        float4 sbv = s4[(lane + it * 32) * 2 + 1];
        float2 q;
        q = __bfloat1622float2(*(const __nv_bfloat162*)&pa.x); sum0 += q.x * sa.x + q.y * sa.y;
        q = __bfloat1622float2(*(const __nv_bfloat162*)&pa.y); sum0 += q.x * sa.z + q.y * sa.w;
        q = __bfloat1622float2(*(const __nv_bfloat162*)&pa.z); sum0 += q.x * sbv.x + q.y * sbv.y;
        q = __bfloat1622float2(*(const __nv_bfloat162*)&pa.w); sum0 += q.x * sbv.z + q.y * sbv.w;
        q = __bfloat1622float2(*(const __nv_bfloat162*)&pb.x); sum1 += q.x * sa.x + q.y * sa.y;
        q = __bfloat1622float2(*(const __nv_bfloat162*)&pb.y); sum1 += q.x * sa.z + q.y * sa.w;
        q = __bfloat1622float2(*(const __nv_bfloat162*)&pb.z); sum1 += q.x * sbv.x + q.y * sbv.y;
        q = __bfloat1622float2(*(const __nv_bfloat162*)&pb.w); sum1 += q.x * sbv.z + q.y * sbv.w;
    }
#pragma unroll
    for (int o = 16; o; o >>= 1) {
        sum0 += __shfl_xor_sync(0xffffffffu, sum0, o);
        sum1 += __shfl_xor_sync(0xffffffffu, sum1, o);
    }
    if (lane == 0) {
        g_logits[z * A_MAX + r0]     = sum0;
        g_logits[z * A_MAX + r0 + 1] = sum1;
        smax[wloc] = fmaxf(sum0, sum1);
    }
    __syncthreads();
    if (threadIdx.x == 0) {
        float m = smax[0];
#pragma unroll
        for (int i = 1; i < 8; ++i) m = fmaxf(m, smax[i]);
        atomicMax(&g_mx[z], fkey(m));
    }
}

// out[z*KDIM + col4] += sum_r e^{l_r - mx} * seq_z[r, col4] (UNNORMALIZED);
// each block also contributes its partial sum of e^{l - mx} to g_sum[z].
__global__ void k_pool(const float* __restrict__ seq1, const float* __restrict__ seq2,
                       float* __restrict__ out, int rowsPerBlock) {
    __shared__ float wsh[32];
    const int z = blockIdx.z;
    const float* seq = z ? seq2 : seq1;
    const int c4 = threadIdx.x;
    const int r0 = blockIdx.y * rowsPerBlock;
    if (threadIdx.x < 32) {
        float mx = fkey_inv(g_mx[z]);
        float e = expf(g_logits[z * A_MAX + r0 + threadIdx.x] - mx);
        wsh[threadIdx.x] = e;
        float t = e;
#pragma unroll
        for (int o = 16; o; o >>= 1) t += __shfl_xor_sync(0xffffffffu, t, o);
        if (threadIdx.x == 0) atomicAdd(&g_sum[z], t);
    }
    __syncthreads();
    float4 acc = {0.f, 0.f, 0.f, 0.f};
    for (int r = 0; r < rowsPerBlock; ++r) {
        float wr = wsh[r];
        float4 v = *(const float4*)(seq + (size_t)(r0 + r) * KDIM + c4 * 4);
        acc.x += wr * v.x; acc.y += wr * v.y; acc.z += wr * v.z; acc.w += wr * v.w;
    }
    float* o = out + z * KDIM + c4 * 4;
    atomicAdd(o + 0, acc.x);
    atomicAdd(o + 1, acc.y);
    atomicAdd(o + 2, acc.z);
    atomicAdd(o + 3, acc.w);
}

// out[i] /= g_sum[z]  (2048 elems)
__global__ void k_norm(float* __restrict__ out) {
    int i = blockIdx.x * blockDim.x + threadIdx.x;
    if (i < 2 * KDIM) out[i] *= (1.f / g_sum[i >> 10]);
}

// ---------------------------------------------------------------------------
extern "C" void kernel_launch(void* const* d_in, const int* in_sizes, int n_in,
                              void* d_out, int out_size) {
    const float* seq1 = (const float*)d_in[0];
    const float* seq2 = (const float*)d_in[1];
    const float* ctx  = (const float*)d_in[2];
    const float* Wc1  = (const float*)d_in[3];
    const float* W1   = (const float*)d_in[4];
    const float* b1   = (const float*)d_in[5];
    const float* Wc2  = (const float*)d_in[6];
    const float* W2   = (const float*)d_in[7];
    const float* b2   = (const float*)d_in[8];
    float* out = (float*)d_out;

    const int a = in_sizes[0] / KDIM;   // 8192
    const int b = in_sizes[1] / KDIM;   // 8192

    cudaFuncSetAttribute(k_proj_mma, cudaFuncAttributeMaxDynamicSharedMemorySize, SMEM_DYN);

    k_prep<<<CVEC_BLOCKS + CONV_BLOCKS, 256>>>(
        (const float4*)seq1, (const float4*)seq2, (const float4*)W1, (const float4*)W2,
        Wc1, Wc2, b1, b2, ctx, out, out_size);

    {
        dim3 g(KDIM / BN, a / BM, 2);
        k_proj_mma<<<g, 256, SMEM_DYN>>>();
    }

    {
        dim3 gm(a / 16, 2);
        k_matvec<<<gm, 256>>>(a);
    }

    {
        const int RPB = 32;
        dim3 gp(1, a / RPB, 2);
        k_pool<<<gp, 256>>>(seq1, seq2, out, RPB);
    }

    k_norm<<<8, 256>>>(out);
}